// round 1
// baseline (speedup 1.0000x reference)
#include <cuda_runtime.h>
#include <cstddef>
#include <cstdint>

// LocalConvolution: out[b,o,i,j] = sum_{c,u,v} x[b,c,i+u,j+v] * w[i,j,o,c,u,v]
// x: [64,64,32,32] f32, w: [28,28,128,64,5,5] f32, out: [64,128,28,28] f32

#define B_  64
#define C_  64
#define H_  32
#define W_  32
#define RR  28
#define CC  28
#define O_  128
#define KH  5
#define KW  5
#define K_  (C_*KH*KW)       // 1600
#define KT  16               // K tile
#define NT  (K_/KT)          // 100
#define WROW 20              // padded row (floats) for w_s: [o][WROW], 80B rows (16B aligned)
#define PROW 68              // padded row (floats) for p_s: [k][PROW]
#define NPOS (RR*CC)         // 784

__device__ __forceinline__ void ffma2(unsigned long long &d,
                                      unsigned long long a,
                                      unsigned long long b) {
    asm("fma.rn.f32x2 %0, %1, %2, %0;" : "+l"(d) : "l"(a), "l"(b));
}

__device__ __forceinline__ unsigned long long rep2(float v) {
    unsigned long long r;
    asm("mov.b64 %0, {%1, %1};" : "=l"(r) : "f"(v));
    return r;
}

__device__ __forceinline__ void cp_async16(void* smem_dst, const void* gmem_src) {
    unsigned dst = (unsigned)__cvta_generic_to_shared(smem_dst);
    asm volatile("cp.async.cg.shared.global [%0], [%1], 16;"
                 :: "r"(dst), "l"(__cvta_generic_to_global(gmem_src)) : "memory");
}

__device__ __forceinline__ void cp_async4(void* smem_dst, const void* gmem_src) {
    unsigned dst = (unsigned)__cvta_generic_to_shared(smem_dst);
    asm volatile("cp.async.ca.shared.global [%0], [%1], 4;"
                 :: "r"(dst), "l"(__cvta_generic_to_global(gmem_src)) : "memory");
}

__global__ __launch_bounds__(256, 3)
void lc_kernel(const float* __restrict__ x,
               const float* __restrict__ w,
               float* __restrict__ out) {
    __shared__ float w_s[2][O_ * WROW];   // 2*128*20*4 = 20480 B
    __shared__ float p_s[2][KT * PROW];   // 2*16*68*4  =  8704 B

    const int pos = blockIdx.x;           // 0..783
    const int i = pos / CC;
    const int j = pos - i * CC;
    const float* wbase = w + (size_t)pos * (O_ * K_);   // [o][k] contiguous, k fastest

    const int tid = threadIdx.x;
    const int tb  = tid >> 4;             // 0..15 -> b group
    const int to  = tid & 15;             // 0..15 -> o group
    const int b0  = tb * 4;

    // --- tile loader (all cp.async; no warp stalls) ---
    auto load_tile = [&](int t, int buf) {
        const int k0 = t * KT;
        // weight: 16k x 128o = 2048 floats = 512 x 16B chunks, 2 per thread.
        // chunk ch: o = ch/4, kc = (ch%4)*4 ; gmem k-contiguous -> smem [o][kc..kc+3]
        #pragma unroll
        for (int cidx = 0; cidx < 2; cidx++) {
            int ch = tid + cidx * 256;
            int o  = ch >> 2;
            int kc = (ch & 3) * 4;
            cp_async16(&w_s[buf][o * WROW + kc], wbase + (size_t)o * K_ + k0 + kc);
        }
        // patch: 16k x 64b = 1024 floats, 4 per thread (one k, 4 consecutive b)
        int kk  = tid >> 4;               // 0..15
        int k   = k0 + kk;
        int cch = k / 25;
        int rem = k - cch * 25;
        int u   = rem / 5;
        int v   = rem - u * 5;
        const float* xk = x + cch * (H_ * W_) + (i + u) * W_ + (j + v);
        int bb = (tid & 15) * 4;
        #pragma unroll
        for (int e = 0; e < 4; e++) {
            cp_async4(&p_s[buf][kk * PROW + bb + e], xk + (size_t)(bb + e) * (C_ * H_ * W_));
        }
    };

    unsigned long long acc[8][2];
    #pragma unroll
    for (int r = 0; r < 8; r++) { acc[r][0] = 0ull; acc[r][1] = 0ull; }

    // prologue
    load_tile(0, 0);
    asm volatile("cp.async.commit_group;" ::: "memory");

    #pragma unroll 1
    for (int t = 0; t < NT; t++) {
        const int buf = t & 1;
        if (t + 1 < NT) {
            load_tile(t + 1, buf ^ 1);
            asm volatile("cp.async.commit_group;" ::: "memory");
            asm volatile("cp.async.wait_group 1;" ::: "memory");
        } else {
            asm volatile("cp.async.wait_group 0;" ::: "memory");
        }
        __syncthreads();

        // compute on buf: per 4-k block read w as float4, p as b-pair LDS.64
        #pragma unroll
        for (int k4 = 0; k4 < KT; k4 += 4) {
            unsigned long long pA[4], pB[4];
            #pragma unroll
            for (int e = 0; e < 4; e++) {
                pA[e] = *(const unsigned long long*)&p_s[buf][(k4 + e) * PROW + b0];
                pB[e] = *(const unsigned long long*)&p_s[buf][(k4 + e) * PROW + b0 + 2];
            }
            #pragma unroll
            for (int r = 0; r < 8; r++) {
                const int o = to + 16 * r;
                float4 wv = *(const float4*)&w_s[buf][o * WROW + k4];
                unsigned long long w0 = rep2(wv.x);
                unsigned long long w1 = rep2(wv.y);
                unsigned long long w2 = rep2(wv.z);
                unsigned long long w3 = rep2(wv.w);
                ffma2(acc[r][0], pA[0], w0); ffma2(acc[r][1], pB[0], w0);
                ffma2(acc[r][0], pA[1], w1); ffma2(acc[r][1], pB[1], w1);
                ffma2(acc[r][0], pA[2], w2); ffma2(acc[r][1], pB[2], w2);
                ffma2(acc[r][0], pA[3], w3); ffma2(acc[r][1], pB[3], w3);
            }
        }
        __syncthreads();
    }

    // epilogue: out[b,o,i,j] = out[(b*O + o)*784 + pos]
    #pragma unroll
    for (int r = 0; r < 8; r++) {
        const int o = to + 16 * r;
        const size_t obase = (size_t)o * NPOS + pos;
        #pragma unroll
        for (int pb = 0; pb < 2; pb++) {
            unsigned long long a = acc[r][pb];
            float lo = __uint_as_float((unsigned)(a & 0xffffffffull));
            float hi = __uint_as_float((unsigned)(a >> 32));
            const int bl = b0 + 2 * pb;
            out[(size_t)bl * (O_ * NPOS) + obase]       = lo;
            out[(size_t)(bl + 1) * (O_ * NPOS) + obase] = hi;
        }
    }
}

extern "C" void kernel_launch(void* const* d_in, const int* in_sizes, int n_in,
                              void* d_out, int out_size) {
    const float* x;
    const float* w;
    // metadata order: x then weight; guard defensively by element counts.
    if (in_sizes[0] == B_ * C_ * H_ * W_) {
        x = (const float*)d_in[0];
        w = (const float*)d_in[1];
    } else {
        x = (const float*)d_in[1];
        w = (const float*)d_in[0];
    }
    float* out = (float*)d_out;
    lc_kernel<<<NPOS, 256>>>(x, w, out);
}

// round 3
// speedup vs baseline: 2.4512x; 2.4512x over previous
#include <cuda_runtime.h>
#include <cstdint>
#include <cstddef>

// LocalConvolution via warp-level bf16 split MMA (mma.sync m16n8k16).
// out[b,o,i,j] = sum_k x_patch[b,k] * w[i,j,o,k], K = 1600 (c,u,v)
// Per CTA (one position pos=i*28+j): D[o=128, b=64] = W[128,K] @ P[64,K]^T

#define B_  64
#define C_  64
#define H_  32
#define W_  32
#define CC  28
#define O_  128
#define K_  1600
#define KT  64
#define NTILES 25
#define NPOS 784

// smem: bf16 tiles, padded rows of 72 bf16 (144 B) for conflict-free ldmatrix
#define ROWB 144
#define WHI_OFF 0
#define WLO_OFF (128*ROWB)               // 18432
#define PHI_OFF (2*128*ROWB)             // 36864
#define PLO_OFF (2*128*ROWB + 64*ROWB)   // 46080
#define SMEM_TOTAL (2*128*ROWB + 2*64*ROWB)  // 55296 bytes

__device__ __forceinline__ uint32_t smem_u32(const void* p) {
    uint32_t a;
    asm("{ .reg .u64 t; cvta.to.shared.u64 t, %1; cvt.u32.u64 %0, t; }" : "=r"(a) : "l"(p));
    return a;
}

// pack: low half = bf16(flo), high half = bf16(fhi)
__device__ __forceinline__ uint32_t cvt2(float flo, float fhi) {
    uint32_t r;
    asm("cvt.rn.bf16x2.f32 %0, %1, %2;" : "=r"(r) : "f"(fhi), "f"(flo));
    return r;
}

__device__ __forceinline__ void ldsm4(uint32_t* r, uint32_t addr) {
    asm volatile("ldmatrix.sync.aligned.m8n8.x4.shared.b16 {%0,%1,%2,%3}, [%4];"
                 : "=r"(r[0]), "=r"(r[1]), "=r"(r[2]), "=r"(r[3]) : "r"(addr));
}

__device__ __forceinline__ void mma16816(float* d, const uint32_t* a, uint32_t b0, uint32_t b1) {
    asm volatile(
        "mma.sync.aligned.m16n8k16.row.col.f32.bf16.bf16.f32 "
        "{%0,%1,%2,%3}, {%4,%5,%6,%7}, {%8,%9}, {%0,%1,%2,%3};"
        : "+f"(d[0]), "+f"(d[1]), "+f"(d[2]), "+f"(d[3])
        : "r"(a[0]), "r"(a[1]), "r"(a[2]), "r"(a[3]), "r"(b0), "r"(b1));
}

__global__ __launch_bounds__(256, 2)
void lc_hmma_kernel(const float* __restrict__ x,
                    const float* __restrict__ w,
                    float* __restrict__ out) {
    extern __shared__ char smem[];
    const uint32_t sbase = smem_u32(smem);

    const int tid = threadIdx.x;
    const int wid = tid >> 5;
    const int l   = tid & 31;

    const int pos = blockIdx.x;
    const int i = pos / CC;
    const int j = pos - i * CC;
    const float* __restrict__ wbase = w + (size_t)pos * (O_ * K_);

    // warp tile: o0 x b0, 32x32
    const int o0 = (wid >> 1) * 32;
    const int b0 = (wid & 1) * 32;

    // loader thread mapping for P: kq = tid&15 (k chunk of 4), bq = tid>>4 (4 b rows)
    const int kq = tid & 15;
    const int bq = tid >> 4;

    // precomputed ldmatrix lane base addresses (byte)
    // A (W tiles): lanes 0-15 -> rows (o) 0-15 k0-7, lanes 16-31 -> k8-15
    const uint32_t aRow = sbase + WHI_OFF
                        + (uint32_t)((o0 + (l & 15)) * ROWB + (l >> 4) * 16);
    // B (P tiles): m = l>>3: n = (l&7) + (l>>4)*8, khalf = (l>>3)&1
    const uint32_t bRow = sbase + PHI_OFF
                        + (uint32_t)((b0 + (l & 7) + ((l >> 4) * 8)) * ROWB
                                     + ((l >> 3) & 1) * 16);

    float acc[2][4][4];
    #pragma unroll
    for (int mi = 0; mi < 2; mi++)
        #pragma unroll
        for (int bt = 0; bt < 4; bt++)
            #pragma unroll
            for (int c = 0; c < 4; c++) acc[mi][bt][c] = 0.0f;

    // ---- W prefetch (tile 0): 128o x 64k = 2048 float4 chunks, 8 per thread ----
    float4 wreg[8];
    #pragma unroll
    for (int ci = 0; ci < 8; ci++) {
        int ch = tid + ci * 256;
        int o = ch >> 4, kc = ch & 15;
        wreg[ci] = *(const float4*)(wbase + (size_t)o * K_ + kc * 4);
    }

    #pragma unroll 1
    for (int t = 0; t < NTILES; t++) {
        const int k0 = t * KT;

        // ---- issue P loads for this tile (L2-resident x) ----
        float preg[4][4];
        {
            int xoff[4];
            #pragma unroll
            for (int e = 0; e < 4; e++) {
                int k = k0 + kq * 4 + e;
                int c = k / 25;
                int rem = k - c * 25;
                int u = rem / 5;
                int v = rem - u * 5;
                xoff[e] = (c * H_ + (i + u)) * W_ + (j + v);
            }
            #pragma unroll
            for (int bi = 0; bi < 4; bi++) {
                const float* xb = x + (size_t)(bq * 4 + bi) * (C_ * H_ * W_);
                #pragma unroll
                for (int e = 0; e < 4; e++) preg[bi][e] = __ldg(xb + xoff[e]);
            }
        }

        // ---- convert + STS W tile (from prefetched regs) ----
        #pragma unroll
        for (int ci = 0; ci < 8; ci++) {
            int ch = tid + ci * 256;
            int o = ch >> 4, kc = ch & 15;
            float4 f = wreg[ci];
            uint32_t h01 = cvt2(f.x, f.y);
            uint32_t h23 = cvt2(f.z, f.w);
            float lo0 = f.x - __uint_as_float(h01 << 16);
            float lo1 = f.y - __uint_as_float(h01 & 0xffff0000u);
            float lo2 = f.z - __uint_as_float(h23 << 16);
            float lo3 = f.w - __uint_as_float(h23 & 0xffff0000u);
            uint32_t l01 = cvt2(lo0, lo1);
            uint32_t l23 = cvt2(lo2, lo3);
            uint32_t off = (uint32_t)o * ROWB + (uint32_t)kc * 8;
            *(uint2*)(smem + WHI_OFF + off) = make_uint2(h01, h23);
            *(uint2*)(smem + WLO_OFF + off) = make_uint2(l01, l23);
        }
        // ---- convert + STS P tile ----
        #pragma unroll
        for (int bi = 0; bi < 4; bi++) {
            float f0 = preg[bi][0], f1 = preg[bi][1], f2 = preg[bi][2], f3 = preg[bi][3];
            uint32_t h01 = cvt2(f0, f1);
            uint32_t h23 = cvt2(f2, f3);
            float lo0 = f0 - __uint_as_float(h01 << 16);
            float lo1 = f1 - __uint_as_float(h01 & 0xffff0000u);
            float lo2 = f2 - __uint_as_float(h23 << 16);
            float lo3 = f3 - __uint_as_float(h23 & 0xffff0000u);
            uint32_t l01 = cvt2(lo0, lo1);
            uint32_t l23 = cvt2(lo2, lo3);
            uint32_t off = (uint32_t)(bq * 4 + bi) * ROWB + (uint32_t)kq * 8;
            *(uint2*)(smem + PHI_OFF + off) = make_uint2(h01, h23);
            *(uint2*)(smem + PLO_OFF + off) = make_uint2(l01, l23);
        }
        __syncthreads();

        // ---- prefetch next W tile (LDGs overlap the MMAs below) ----
        if (t + 1 < NTILES) {
            const float* wt = wbase + k0 + KT;
            #pragma unroll
            for (int ci = 0; ci < 8; ci++) {
                int ch = tid + ci * 256;
                int o = ch >> 4, kc = ch & 15;
                wreg[ci] = *(const float4*)(wt + (size_t)o * K_ + kc * 4);
            }
        }

        // ---- compute: 4 k-steps of 16, 3 split combos ----
        #pragma unroll
        for (int ks = 0; ks < 4; ks++) {
            const uint32_t colb = (uint32_t)ks * 32;
            uint32_t ah[2][4], al[2][4], bh[2][4], bl[2][4];
            ldsm4(ah[0], aRow + colb);
            ldsm4(ah[1], aRow + colb + 16 * ROWB);
            ldsm4(al[0], aRow + colb + (WLO_OFF - WHI_OFF));
            ldsm4(al[1], aRow + colb + (WLO_OFF - WHI_OFF) + 16 * ROWB);
            ldsm4(bh[0], bRow + colb);
            ldsm4(bh[1], bRow + colb + 16 * ROWB);
            ldsm4(bl[0], bRow + colb + (PLO_OFF - PHI_OFF));
            ldsm4(bl[1], bRow + colb + (PLO_OFF - PHI_OFF) + 16 * ROWB);
            #pragma unroll
            for (int mi = 0; mi < 2; mi++) {
                #pragma unroll
                for (int bt = 0; bt < 4; bt++) {
                    const int g = bt >> 1, p = (bt & 1) * 2;
                    mma16816(acc[mi][bt], ah[mi], bh[g][p], bh[g][p + 1]);
                    mma16816(acc[mi][bt], ah[mi], bl[g][p], bl[g][p + 1]);
                    mma16816(acc[mi][bt], al[mi], bh[g][p], bh[g][p + 1]);
                }
            }
        }
        __syncthreads();
    }

    // ---- epilogue: D frag (mi,bt): o = o0+mi*16+(l>>2)+8*(c>>1), b = b0+bt*8+(l&3)*2+(c&1)
    const int orow = l >> 2;
    const int bcol = (l & 3) * 2;
    #pragma unroll
    for (int mi = 0; mi < 2; mi++) {
        #pragma unroll
        for (int bt = 0; bt < 4; bt++) {
            #pragma unroll
            for (int c = 0; c < 4; c++) {
                int o = o0 + mi * 16 + orow + (c >> 1) * 8;
                int b = b0 + bt * 8 + bcol + (c & 1);
                out[((size_t)b * O_ + o) * NPOS + pos] = acc[mi][bt][c];
            }
        }
    }
}

extern "C" void kernel_launch(void* const* d_in, const int* in_sizes, int n_in,
                              void* d_out, int out_size) {
    const float* x;
    const float* w;
    if (in_sizes[0] == B_ * C_ * H_ * W_) {
        x = (const float*)d_in[0];
        w = (const float*)d_in[1];
    } else {
        x = (const float*)d_in[1];
        w = (const float*)d_in[0];
    }
    float* out = (float*)d_out;
    cudaFuncSetAttribute(lc_hmma_kernel, cudaFuncAttributeMaxDynamicSharedMemorySize, SMEM_TOTAL);
    lc_hmma_kernel<<<NPOS, 256, SMEM_TOTAL>>>(x, w, out);
}